// round 16
// baseline (speedup 1.0000x reference)
#include <cuda_runtime.h>
#include <cuda_fp16.h>
#include <cstdint>
#include <math.h>

#define NN 100000
#define NE 1600000
#define EPS 1e-5f
#define HISTB 1563

// ================= device scratch =================
__device__ int    g_cnt[NN];
__device__ int    g_done[1];
__device__ int    g_off[NN + 1];
__device__ int    g_cur[NN];
__device__ float  g_inv[NN];
__device__ int    g_col[NE];
__device__ __half g_x16[(size_t)NN * 128];     // fp16 x (layer-0 inputs)
__device__ __half g_h16[(size_t)NN * 128];     // fp16 relu(bn(pre)) (layers 1,2)
__device__ __half g_agg16[(size_t)NN * 128];   // fp16 aggregation result
__device__ __half g_w16[81920];                // fp16 weights, all layers
__device__ float  g_preA[(size_t)NN * 128];
__device__ float  g_preB[(size_t)NN * 128];
__device__ float  g_sum[128];
__device__ float  g_ssq[128];

#define WL0 0
#define WR0 16384
#define WL1 32768
#define WR1 49152
#define WL2 65536
#define WR2 73728

__device__ __forceinline__ uint32_t h2u(float a, float b) {
    __half2 h = __floats2half2_rn(a, b);
    return *(uint32_t*)&h;
}
__device__ __forceinline__ void cp_async16(uint32_t dst, const void* src, int srcsize) {
    asm volatile("cp.async.cg.shared.global [%0], [%1], 16, %2;"
                 :: "r"(dst), "l"(src), "r"(srcsize) : "memory");
}
#define CP_COMMIT() asm volatile("cp.async.commit_group;" ::: "memory")
#define CP_WAIT(n)  asm volatile("cp.async.wait_group %0;" :: "n"(n) : "memory")

// ========== histscan: blocks 1..HISTB histogram; block 0 waits + scans =====
// Also: block 0 threads convert nothing; weight conversion handled by a
// dedicated block (blockIdx == HISTB+1).
__global__ void histscan_kernel(const int* __restrict__ dst,
                                const float* __restrict__ Wl0, const float* __restrict__ Wr0,
                                const float* __restrict__ Wl1, const float* __restrict__ Wr1,
                                const float* __restrict__ Wl2, const float* __restrict__ Wr2) {
    const int t = threadIdx.x;
    if (blockIdx.x == HISTB + 1) {             // weight fp16 conversion
        for (int i = t; i < 16384; i += 1024) {
            g_w16[WL0 + i] = __float2half_rn(Wl0[i]);
            g_w16[WR0 + i] = __float2half_rn(Wr0[i]);
            g_w16[WL1 + i] = __float2half_rn(Wl1[i]);
            g_w16[WR1 + i] = __float2half_rn(Wr1[i]);
        }
        for (int i = t; i < 8192; i += 1024) {
            g_w16[WL2 + i] = __float2half_rn(Wl2[i]);
            g_w16[WR2 + i] = __float2half_rn(Wr2[i]);
        }
        return;
    }
    if (blockIdx.x > 0) {                      // histogram
        int e = (blockIdx.x - 1) * 1024 + t;
        if (e < NE) atomicAdd(&g_cnt[dst[e]], 1);
        __syncthreads();
        __threadfence();
        if (t == 0) atomicAdd(&g_done[0], 1);
        return;
    }
    // ---- block 0: wait for all histogram blocks, then exclusive scan ----
    if (t == 0) {
        while (*(volatile int*)&g_done[0] < HISTB) __nanosleep(128);
    }
    __syncthreads();
    __threadfence();
    __shared__ int s[1024];
    const int chunk = (NN + 1023) / 1024;
    int start = t * chunk;
    int end = start + chunk; if (end > NN) end = NN;
    if (start > NN) start = NN;
    int sum = 0;
    for (int i = start; i < end; i++) sum += g_cnt[i];
    s[t] = sum;
    __syncthreads();
    for (int off = 1; off < 1024; off <<= 1) {
        int v = (t >= off) ? s[t - off] : 0;
        __syncthreads();
        s[t] += v;
        __syncthreads();
    }
    int excl = (t == 0) ? 0 : s[t - 1];
    for (int i = start; i < end; i++) {
        int c = g_cnt[i];
        g_off[i] = excl;
        g_cur[i] = excl;
        g_inv[i] = 1.0f / fmaxf((float)c, 1.0f);
        excl += c;
    }
    if (t == 1023) g_off[NN] = s[1023];
}

// blocks [0,6250): CSR fill.  blocks [6250,18750): x -> fp16 mirror.
__global__ void fill_kernel(const int* __restrict__ src, const int* __restrict__ dst,
                            const float* __restrict__ x) {
    if (blockIdx.x < 6250) {
        int e = blockIdx.x * blockDim.x + threadIdx.x;
        if (e < NE) {
            int d = dst[e];
            int p = atomicAdd(&g_cur[d], 1);
            g_col[p] = src[e];
        }
        return;
    }
    int i = (blockIdx.x - 6250) * blockDim.x + threadIdx.x;   // over NN*32
    float4 v = ((const float4*)x)[i];
    ((uint2*)g_x16)[i] = make_uint2(h2u(v.x, v.y), h2u(v.z, v.w));
}

// ====== mean aggregation (warp/node), fp16 in -> fp16 out, stats-zero ======
__global__ void agg_kernel(const __half* __restrict__ hin) {
    if (blockIdx.x == 0 && threadIdx.x < 128) {
        g_sum[threadIdx.x] = 0.f;
        g_ssq[threadIdx.x] = 0.f;
    }
    int w = (blockIdx.x * blockDim.x + threadIdx.x) >> 5;
    if (w >= NN) return;
    int lane = threadIdx.x & 31;
    const uint2* h2p = (const uint2*)hin;      // 4 halves per lane
    float4 acc = make_float4(0.f, 0.f, 0.f, 0.f);
    int e0 = g_off[w], e1 = g_off[w + 1];
    for (int j = e0; j < e1; j++) {
        int s = g_col[j];
        uint2 u = __ldg(&h2p[(size_t)s * 32 + lane]);
        float2 f0 = __half22float2(*(__half2*)&u.x);
        float2 f1 = __half22float2(*(__half2*)&u.y);
        acc.x += f0.x; acc.y += f0.y; acc.z += f1.x; acc.w += f1.y;
    }
    float iv = g_inv[w];
    ((uint2*)g_agg16)[(size_t)w * 32 + lane] =
        make_uint2(h2u(acc.x * iv, acc.y * iv), h2u(acc.z * iv, acc.w * iv));
}

// ===== fp16 mma.sync dual-GEMM, 4-stage cp.async pipeline, occupancy 2 =====
// (byte-identical structure to the measured-best 639us version)
template <int COUT>
__global__ __launch_bounds__(256, 2) void gemm_mma_kernel(
    const __half* __restrict__ Aagg, const __half* __restrict__ Aroot,
    const __half* __restrict__ wl, const __half* __restrict__ wr,
    const float* __restrict__ bias, float* __restrict__ outp)
{
    constexpr int STRW = 20;
    constexpr int ABUF = 128 * STRW;
    constexpr int BBUF = COUT * STRW;
    constexpr int STG = ABUF + BBUF;
    constexpr int NT = COUT / 16;
    extern __shared__ uint32_t smem32[];
    const uint32_t sbase = (uint32_t)__cvta_generic_to_shared(smem32);

    const int tid = threadIdx.x, wid = tid >> 5, lane = tid & 31;
    const int g = lane >> 2, tig = lane & 3;
    const int row0 = blockIdx.x * 128;
    const int m0 = (wid >> 1) * 32;
    const int n0 = (wid & 1) * (COUT / 2);

    auto stage = [&](int c, int b) {
        const __half* srcA = (c < 4) ? Aagg : Aroot;
        const __half* srcB = (c < 4) ? wl : wr;
        const int koff = (c & 3) * 32;
#pragma unroll
        for (int t = 0; t < 2; t++) {
            int i = tid + t * 256;
            int row = i >> 2, q = i & 3;
            int grow = row0 + row;
            uint32_t dst = sbase + 4 * (b * STG + row * STRW + q * 4);
            cp_async16(dst, srcA + (size_t)grow * 128 + koff + q * 8,
                       grow < NN ? 16 : 0);
        }
#pragma unroll
        for (int t = 0; t < COUT / 64; t++) {
            int i = tid + t * 256;
            int n = i >> 2, q = i & 3;
            uint32_t dst = sbase + 4 * (b * STG + ABUF + n * STRW + q * 4);
            cp_async16(dst, srcB + n * 128 + koff + q * 8, 16);
        }
        CP_COMMIT();
    };

    float acc[2][NT][4];
#pragma unroll
    for (int mt = 0; mt < 2; mt++)
#pragma unroll
        for (int nt = 0; nt < NT; nt++)
#pragma unroll
            for (int j = 0; j < 4; j++) acc[mt][nt][j] = 0.f;

    stage(0, 0);
    stage(1, 1);
    stage(2, 2);

#pragma unroll 1
    for (int c = 0; c < 8; c++) {
        if (c < 6)       CP_WAIT(2);
        else if (c == 6) CP_WAIT(1);
        else             CP_WAIT(0);
        __syncthreads();

        const uint32_t* Ab = smem32 + (c & 3) * STG;
        const uint32_t* Bb = Ab + ABUF;
#pragma unroll
        for (int ks = 0; ks < 2; ks++) {
            const int kk2 = ks * 8;
            uint32_t a[2][4], b[NT][2];
#pragma unroll
            for (int mt = 0; mt < 2; mt++) {
                const uint32_t* ap = Ab + (m0 + mt * 16 + g) * STRW + kk2 + tig;
                a[mt][0] = ap[0];
                a[mt][1] = ap[8 * STRW];
                a[mt][2] = ap[4];
                a[mt][3] = ap[8 * STRW + 4];
            }
#pragma unroll
            for (int nt = 0; nt < NT; nt++) {
                const uint32_t* bp = Bb + (n0 + nt * 8 + g) * STRW + kk2 + tig;
                b[nt][0] = bp[0];
                b[nt][1] = bp[4];
            }
#pragma unroll
            for (int mt = 0; mt < 2; mt++)
#pragma unroll
                for (int nt = 0; nt < NT; nt++)
                    asm volatile(
                        "mma.sync.aligned.m16n8k16.row.col.f32.f16.f16.f32 "
                        "{%0,%1,%2,%3}, {%4,%5,%6,%7}, {%8,%9}, {%0,%1,%2,%3};"
                        : "+f"(acc[mt][nt][0]), "+f"(acc[mt][nt][1]),
                          "+f"(acc[mt][nt][2]), "+f"(acc[mt][nt][3])
                        : "r"(a[mt][0]), "r"(a[mt][1]), "r"(a[mt][2]), "r"(a[mt][3]),
                          "r"(b[nt][0]), "r"(b[nt][1]));
        }
        if (c + 3 < 8) stage(c + 3, (c + 3) & 3);
    }

    // ---- epilogue: bias + store + fused BN stats ----
    float ssum[NT][2], sq[NT][2];
#pragma unroll
    for (int nt = 0; nt < NT; nt++) {
        ssum[nt][0] = ssum[nt][1] = 0.f;
        sq[nt][0] = sq[nt][1] = 0.f;
    }
#pragma unroll
    for (int mt = 0; mt < 2; mt++) {
        int rA2 = row0 + m0 + mt * 16 + g;
        int rB2 = rA2 + 8;
#pragma unroll
        for (int nt = 0; nt < NT; nt++) {
            int col = n0 + nt * 8 + tig * 2;
            float b0 = bias[col], b1 = bias[col + 1];
            float o00 = acc[mt][nt][0] + b0, o01 = acc[mt][nt][1] + b1;
            float o10 = acc[mt][nt][2] + b0, o11 = acc[mt][nt][3] + b1;
            if (rA2 < NN) {
                *(float2*)(outp + (size_t)rA2 * COUT + col) = make_float2(o00, o01);
                ssum[nt][0] += o00; sq[nt][0] += o00 * o00;
                ssum[nt][1] += o01; sq[nt][1] += o01 * o01;
            }
            if (rB2 < NN) {
                *(float2*)(outp + (size_t)rB2 * COUT + col) = make_float2(o10, o11);
                ssum[nt][0] += o10; sq[nt][0] += o10 * o10;
                ssum[nt][1] += o11; sq[nt][1] += o11 * o11;
            }
        }
    }
#pragma unroll
    for (int nt = 0; nt < NT; nt++)
#pragma unroll
        for (int j = 0; j < 2; j++) {
            float s = ssum[nt][j], q = sq[nt][j];
#pragma unroll
            for (int off = 4; off < 32; off <<= 1) {
                s += __shfl_xor_sync(0xFFFFFFFFu, s, off);
                q += __shfl_xor_sync(0xFFFFFFFFu, q, off);
            }
            if (g == 0) {
                int col = n0 + nt * 8 + tig * 2 + j;
                atomicAdd(&g_sum[col], s);
                atomicAdd(&g_ssq[col], q);
            }
        }
}

// ====== norm16: relu(bn(pre)) -> fp16 h16 (computes scale/shift inline) ====
__global__ void norm16_kernel(const float* __restrict__ inp,
                              const float* __restrict__ gamma,
                              const float* __restrict__ beta) {
    __shared__ float ssc[128], ssh[128];
    if (threadIdx.x < 128) {
        int c = threadIdx.x;
        float m = g_sum[c] * (1.0f / (float)NN);
        float v = g_ssq[c] * (1.0f / (float)NN) - m * m;
        float s = gamma[c] * rsqrtf(v + EPS);
        ssc[c] = s;
        ssh[c] = beta[c] - m * s;
    }
    __syncthreads();
    const int total4 = NN * 32;
    const float4* p4 = (const float4*)inp;
    uint2* o2 = (uint2*)g_h16;
    for (int i = blockIdx.x * blockDim.x + threadIdx.x; i < total4;
         i += gridDim.x * blockDim.x) {
        int c = (i * 4) & 127;
        float4 v = p4[i];
        float4 sc = *(const float4*)(ssc + c);
        float4 sh = *(const float4*)(ssh + c);
        float r0 = fmaxf(fmaf(v.x, sc.x, sh.x), 0.f);
        float r1 = fmaxf(fmaf(v.y, sc.y, sh.y), 0.f);
        float r2 = fmaxf(fmaf(v.z, sc.z, sh.z), 0.f);
        float r3 = fmaxf(fmaf(v.w, sc.w, sh.w), 0.f);
        o2[i] = make_uint2(h2u(r0, r1), h2u(r2, r3));
    }
}
// ====== final bn (no relu) -> fp32 out (C=64, scale/shift inline) ======
__global__ void norm_kernel(const float* __restrict__ inp,
                            const float* __restrict__ gamma,
                            const float* __restrict__ beta,
                            float* __restrict__ outp) {
    __shared__ float ssc[64], ssh[64];
    if (threadIdx.x < 64) {
        int c = threadIdx.x;
        float m = g_sum[c] * (1.0f / (float)NN);
        float v = g_ssq[c] * (1.0f / (float)NN) - m * m;
        float s = gamma[c] * rsqrtf(v + EPS);
        ssc[c] = s;
        ssh[c] = beta[c] - m * s;
    }
    __syncthreads();
    const int total4 = NN * 16;
    const float4* p4 = (const float4*)inp;
    float4* o4 = (float4*)outp;
    for (int i = blockIdx.x * blockDim.x + threadIdx.x; i < total4;
         i += gridDim.x * blockDim.x) {
        int c = (i * 4) & 63;
        float4 v = p4[i];
        float4 sc = *(const float4*)(ssc + c);
        float4 sh = *(const float4*)(ssh + c);
        float4 r;
        r.x = fmaf(v.x, sc.x, sh.x); r.y = fmaf(v.y, sc.y, sh.y);
        r.z = fmaf(v.z, sc.z, sh.z); r.w = fmaf(v.w, sc.w, sh.w);
        o4[i] = r;
    }
}

// ================= launch =================
extern "C" void kernel_launch(void* const* d_in, const int* in_sizes, int n_in,
                              void* d_out, int out_size) {
    const float* x    = (const float*)d_in[0];
    const int*   ei   = (const int*)d_in[1];
    const int*   esrc = ei;
    const int*   edst = ei + NE;
    const float* Wl0 = (const float*)d_in[2];
    const float* bl0 = (const float*)d_in[3];
    const float* Wr0 = (const float*)d_in[4];
    const float* ga0 = (const float*)d_in[5];
    const float* be0 = (const float*)d_in[6];
    const float* Wl1 = (const float*)d_in[7];
    const float* bl1 = (const float*)d_in[8];
    const float* Wr1 = (const float*)d_in[9];
    const float* ga1 = (const float*)d_in[10];
    const float* be1 = (const float*)d_in[11];
    const float* Wl2 = (const float*)d_in[12];
    const float* bl2 = (const float*)d_in[13];
    const float* Wr2 = (const float*)d_in[14];
    const float* ga2 = (const float*)d_in[15];
    const float* be2 = (const float*)d_in[16];
    float* out = (float*)d_out;

    const int smem128 = 4 * (128 * 20 + 128 * 20) * 4;  // 81920
    const int smem64  = 4 * (128 * 20 + 64 * 20) * 4;   // 61440
    cudaFuncSetAttribute(gemm_mma_kernel<128>, cudaFuncAttributeMaxDynamicSharedMemorySize, smem128);
    cudaFuncSetAttribute(gemm_mma_kernel<64>,  cudaFuncAttributeMaxDynamicSharedMemorySize, smem64);

    float *preA = nullptr, *preB = nullptr;
    int *cntp = nullptr, *donep = nullptr;
    __half *x16 = nullptr, *h16 = nullptr, *agg16 = nullptr, *w16 = nullptr;
    cudaGetSymbolAddress((void**)&preA, g_preA);
    cudaGetSymbolAddress((void**)&preB, g_preB);
    cudaGetSymbolAddress((void**)&cntp, g_cnt);
    cudaGetSymbolAddress((void**)&donep, g_done);
    cudaGetSymbolAddress((void**)&x16, g_x16);
    cudaGetSymbolAddress((void**)&h16, g_h16);
    cudaGetSymbolAddress((void**)&agg16, g_agg16);
    cudaGetSymbolAddress((void**)&w16, g_w16);

    // ---- CSR build (memsets are graph memset nodes, not kernel launches) ----
    cudaMemsetAsync(cntp, 0, NN * sizeof(int));
    cudaMemsetAsync(donep, 0, sizeof(int));
    histscan_kernel<<<HISTB + 2, 1024>>>(edst, Wl0, Wr0, Wl1, Wr1, Wl2, Wr2);
    fill_kernel<<<6250 + 12500, 256>>>(esrc, edst, x);

    const int aggBlocks = NN / 8;
    const int gemmBlocks = (NN + 127) / 128;

    // ---- layer 0 ----
    agg_kernel<<<aggBlocks, 256>>>(x16);
    gemm_mma_kernel<128><<<gemmBlocks, 256, smem128>>>(agg16, x16, w16 + WL0, w16 + WR0, bl0, preA);
    norm16_kernel<<<2048, 256>>>(preA, ga0, be0);

    // ---- layer 1 ----
    agg_kernel<<<aggBlocks, 256>>>(h16);
    gemm_mma_kernel<128><<<gemmBlocks, 256, smem128>>>(agg16, h16, w16 + WL1, w16 + WR1, bl1, preB);
    norm16_kernel<<<2048, 256>>>(preB, ga1, be1);

    // ---- layer 2 ----
    agg_kernel<<<aggBlocks, 256>>>(h16);
    gemm_mma_kernel<64><<<gemmBlocks, 256, smem64>>>(agg16, h16, w16 + WL2, w16 + WR2, bl2, preA);

    // ---- final normalize (no relu) ----
    norm_kernel<<<2048, 256>>>(preA, ga2, be2, out);
}